// round 16
// baseline (speedup 1.0000x reference)
#include <cuda_runtime.h>
#include <cuda_fp16.h>

#define BB 4
#define SS_DIM 1024
#define XX 1024
#define CC 8
#define DD 2
#define WIDTH 16
#define DEPTH 4
#define TPB 128
#define SHALF 512
#define NCHUNK (SHALF / 32)

// pack two f32 -> f16x2; e0 lands in LOWER half
__device__ __forceinline__ unsigned pack_f16x2(float e0, float e1) {
    unsigned d; asm("cvt.rn.f16x2.f32 %0, %1, %2;" : "=r"(d) : "f"(e1), "f"(e0)); return d;
}
__device__ __forceinline__ unsigned tanh2(unsigned x) {
    unsigned d; asm("tanh.approx.f16x2 %0, %1;" : "=r"(d) : "r"(x)); return d;
}
__device__ __forceinline__ unsigned hadd2(unsigned a, unsigned b) {
    unsigned d; asm("add.rn.f16x2 %0, %1, %2;" : "=r"(d) : "r"(a), "r"(b)); return d;
}
__device__ __forceinline__ unsigned hfma2(unsigned a, unsigned b, unsigned c) {
    unsigned d; asm("fma.rn.f16x2 %0, %1, %2, %3;" : "=r"(d) : "r"(a), "r"(b), "r"(c)); return d;
}
__device__ __forceinline__ float f16lo(unsigned p) {
    __half2 h = *reinterpret_cast<__half2*>(&p); return __half2float(__low2half(h));
}
__device__ __forceinline__ float f16hi(unsigned p) {
    __half2 h = *reinterpret_cast<__half2*>(&p); return __half2float(__high2half(h));
}
__device__ __forceinline__ void mma_f16_init(float* d, const unsigned* a,
                                             unsigned b0, unsigned b1,
                                             float c0, float c1) {
    asm("mma.sync.aligned.m16n8k16.row.col.f32.f16.f16.f32 "
        "{%0,%1,%2,%3}, {%4,%5,%6,%7}, {%8,%9}, {%10,%11,%10,%11};"
        : "=f"(d[0]), "=f"(d[1]), "=f"(d[2]), "=f"(d[3])
        : "r"(a[0]), "r"(a[1]), "r"(a[2]), "r"(a[3]), "r"(b0), "r"(b1),
          "f"(c0), "f"(c1));
}

__global__ __launch_bounds__(TPB, 6)
void ccl_kernel(const float* __restrict__ yu,
                const float* __restrict__ xin,
                const float* __restrict__ gWin,
                const float* __restrict__ gbin,
                const float* __restrict__ gWhid,
                const float* __restrict__ gbhid,
                const float* __restrict__ gWout,
                const float* __restrict__ gbout,
                float* __restrict__ out) {
    __shared__ float  s_u[SHALF][CC];      // 16KB
    __shared__ float2 s_y[SHALF];          // 4KB

    const int t    = threadIdx.x;
    const int warp = t >> 5;
    const int lane = t & 31;
    const int g    = lane >> 2;
    const int q    = lane & 3;
    const int b    = blockIdx.z;
    const int sb   = blockIdx.y * SHALF;
    const int xi   = blockIdx.x * 4 + warp;

    // ---- stage this block's yu half ----
    for (int i = t; i < SHALF; i += TPB) {
        const float2* row = (const float2*)(yu + ((size_t)b * SS_DIM + sb + i) * (CC + DD));
        const float2 a0 = row[0], a1 = row[1], a2 = row[2], a3 = row[3], yv = row[4];
        float2* ur = (float2*)&s_u[i][0];
        ur[0] = a0; ur[1] = a1; ur[2] = a2; ur[3] = a3;
        s_y[i] = yv;
    }
    __syncthreads();

    const float bout = gbout[0];

    // ---- register-resident per-lane constants (all loop-invariant) ----
    const int j0 = 2 * q, j2 = 8 + 2 * q;
    const unsigned wp0 = pack_f16x2(gWin[j0], gWin[j0 + 1]);
    const unsigned wp1 = pack_f16x2(gWin[j2], gWin[j2 + 1]);
    const unsigned bp0 = pack_f16x2(gbin[j0], gbin[j0 + 1]);
    const unsigned bp1 = pack_f16x2(gbin[j2], gbin[j2 + 1]);
    const float2 woA = make_float2(gWout[j0], gWout[j0 + 1]);
    const float2 woB = make_float2(gWout[j2], gWout[j2 + 1]);

    float2 bh[DEPTH][2];
#pragma unroll
    for (int l = 0; l < DEPTH; ++l) {
        bh[l][0] = make_float2(gbhid[l * WIDTH + j0], gbhid[l * WIDTH + j0 + 1]);
        bh[l][1] = make_float2(gbhid[l * WIDTH + j2], gbhid[l * WIDTH + j2 + 1]);
    }

    // B fragments, single fp16
    unsigned Bf[DEPTH][2][2];
#pragma unroll
    for (int l = 0; l < DEPTH; ++l) {
        const float* Wl = gWhid + l * WIDTH * WIDTH;
#pragma unroll
        for (int nt = 0; nt < 2; ++nt) {
            const int n = g + 8 * nt;
            Bf[l][nt][0] = pack_f16x2(Wl[(2 * q) * WIDTH + n],
                                      Wl[(2 * q + 1) * WIDTH + n]);
            Bf[l][nt][1] = pack_f16x2(Wl[(2 * q + 8) * WIDTH + n],
                                      Wl[(2 * q + 9) * WIDTH + n]);
        }
    }

    const float2 xv = *(const float2*)(xin + ((size_t)b * XX + xi) * DD);

    float acc0 = 0.0f, acc1 = 0.0f;

#pragma unroll 1
    for (int ch = 0; ch < NCHUNK; ++ch) {
        const int s0 = ch * 32;

        const float2 yv = s_y[s0 + lane];
        const float dx0 = xv.x - yv.x;
        const float dx1 = xv.y - yv.y;
        const float r = fmaf(dx1, dx1, dx0 * dx0);
        const float r0 = __shfl_sync(0xffffffffu, r, g);
        const float r1 = __shfl_sync(0xffffffffu, r, g + 8);
        const float r2 = __shfl_sync(0xffffffffu, r, g + 16);
        const float r3 = __shfl_sync(0xffffffffu, r, g + 24);

        // h lives in f16x2 A-fragment layout: A[mt][0..3]
        const unsigned rd0 = pack_f16x2(r0, r0);
        const unsigned rd1 = pack_f16x2(r1, r1);
        const unsigned rd2 = pack_f16x2(r2, r2);
        const unsigned rd3 = pack_f16x2(r3, r3);
        unsigned A[2][4];
        A[0][0] = hfma2(rd0, wp0, bp0);  A[0][1] = hfma2(rd1, wp0, bp0);
        A[0][2] = hfma2(rd0, wp1, bp1);  A[0][3] = hfma2(rd1, wp1, bp1);
        A[1][0] = hfma2(rd2, wp0, bp0);  A[1][1] = hfma2(rd3, wp0, bp0);
        A[1][2] = hfma2(rd2, wp1, bp1);  A[1][3] = hfma2(rd3, wp1, bp1);

#pragma unroll
        for (int l = 0; l < DEPTH; ++l) {
#pragma unroll
            for (int mt = 0; mt < 2; ++mt) {
                // both mmas read the OLD A before any update (RAW-safe)
                float z0[4], z1[4];
                mma_f16_init(z0, A[mt], Bf[l][0][0], Bf[l][0][1],
                             bh[l][0].x, bh[l][0].y);
                mma_f16_init(z1, A[mt], Bf[l][1][0], Bf[l][1][1],
                             bh[l][1].x, bh[l][1].y);
                A[mt][0] = hadd2(A[mt][0], tanh2(pack_f16x2(z0[0], z0[1])));
                A[mt][1] = hadd2(A[mt][1], tanh2(pack_f16x2(z0[2], z0[3])));
                A[mt][2] = hadd2(A[mt][2], tanh2(pack_f16x2(z1[0], z1[1])));
                A[mt][3] = hadd2(A[mt][3], tanh2(pack_f16x2(z1[2], z1[3])));
            }
        }

        // k = h @ Wout + bout (f32 dot from f16 h), quad-reduce
        float k[4];
#pragma unroll
        for (int mt = 0; mt < 2; ++mt) {
            float pg  = fmaf(f16lo(A[mt][0]), woA.x,
                        fmaf(f16hi(A[mt][0]), woA.y,
                        fmaf(f16lo(A[mt][2]), woB.x, f16hi(A[mt][2]) * woB.y)));
            float pg8 = fmaf(f16lo(A[mt][1]), woA.x,
                        fmaf(f16hi(A[mt][1]), woA.y,
                        fmaf(f16lo(A[mt][3]), woB.x, f16hi(A[mt][3]) * woB.y)));
            pg  += __shfl_xor_sync(0xffffffffu, pg, 1);
            pg  += __shfl_xor_sync(0xffffffffu, pg, 2);
            pg8 += __shfl_xor_sync(0xffffffffu, pg8, 1);
            pg8 += __shfl_xor_sync(0xffffffffu, pg8, 2);
            k[2 * mt]     = pg + bout;
            k[2 * mt + 1] = pg8 + bout;
        }

        const int srow[4] = {s0 + g, s0 + g + 8, s0 + 16 + g, s0 + 24 + g};
#pragma unroll
        for (int i = 0; i < 4; ++i) {
            const float2 uv = *(const float2*)&s_u[srow[i]][2 * q];
            acc0 = fmaf(k[i], uv.x, acc0);
            acc1 = fmaf(k[i], uv.y, acc1);
        }
    }

#pragma unroll
    for (int off = 4; off < 32; off <<= 1) {
        acc0 += __shfl_xor_sync(0xffffffffu, acc0, off);
        acc1 += __shfl_xor_sync(0xffffffffu, acc1, off);
    }
    if (lane < 4) {
        const float invS = 1.0f / (float)SS_DIM;
        float* op = out + ((size_t)b * XX + xi) * CC + 2 * lane;
        atomicAdd(op,     acc0 * invS);
        atomicAdd(op + 1, acc1 * invS);
    }
}

extern "C" void kernel_launch(void* const* d_in, const int* in_sizes, int n_in,
                              void* d_out, int out_size) {
    const float* yu    = (const float*)d_in[0]; // (4,1024,10)
    const float* x     = (const float*)d_in[1]; // (4,1024,2)
    const float* W_in  = (const float*)d_in[2]; // (1,16)
    const float* b_in  = (const float*)d_in[3]; // (16,)
    const float* W_hid = (const float*)d_in[4]; // (4,16,16)
    const float* b_hid = (const float*)d_in[5]; // (4,16)
    const float* W_out = (const float*)d_in[6]; // (16,1)
    const float* b_out = (const float*)d_in[7]; // (1,)

    (void)in_sizes; (void)n_in;

    cudaMemsetAsync(d_out, 0, (size_t)out_size * sizeof(float), 0);

    dim3 grid(XX / 4, SS_DIM / SHALF, BB);   // 2048 blocks
    ccl_kernel<<<grid, TPB, 0, 0>>>(yu, x, W_in, b_in, W_hid, b_hid, W_out, b_out,
                                    (float*)d_out);
}

// round 17
// speedup vs baseline: 1.0051x; 1.0051x over previous
#include <cuda_runtime.h>
#include <cuda_fp16.h>

#define BB 4
#define SS_DIM 1024
#define XX 1024
#define CC 8
#define DD 2
#define WIDTH 16
#define DEPTH 4
#define TPB 128
#define SHALF 512
#define NPAIR (SHALF / 64)   // 8 chunk-pairs; streams at s and s+256

__device__ __forceinline__ float fast_tanh(float x) {
    float y; asm("tanh.approx.f32 %0, %1;" : "=f"(y) : "f"(x)); return y;
}
// pack two f32 -> f16x2; e0 lands in LOWER half
__device__ __forceinline__ unsigned pack_f16x2(float e0, float e1) {
    unsigned d; asm("cvt.rn.f16x2.f32 %0, %1, %2;" : "=r"(d) : "f"(e1), "f"(e0)); return d;
}
__device__ __forceinline__ void mma_f16_init(float* d, const unsigned* a,
                                             unsigned b0, unsigned b1,
                                             float c0, float c1) {
    asm("mma.sync.aligned.m16n8k16.row.col.f32.f16.f16.f32 "
        "{%0,%1,%2,%3}, {%4,%5,%6,%7}, {%8,%9}, {%10,%11,%10,%11};"
        : "=f"(d[0]), "=f"(d[1]), "=f"(d[2]), "=f"(d[3])
        : "r"(a[0]), "r"(a[1]), "r"(a[2]), "r"(a[3]), "r"(b0), "r"(b1),
          "f"(c0), "f"(c1));
}

__global__ __launch_bounds__(TPB, 4)
void ccl_kernel(const float* __restrict__ yu,
                const float* __restrict__ xin,
                const float* __restrict__ gWin,
                const float* __restrict__ gbin,
                const float* __restrict__ gWhid,
                const float* __restrict__ gbhid,
                const float* __restrict__ gWout,
                const float* __restrict__ gbout,
                float* __restrict__ out) {
    __shared__ float  s_u[SHALF][CC];      // 16KB
    __shared__ float2 s_y[SHALF];          // 4KB

    const int t    = threadIdx.x;
    const int warp = t >> 5;
    const int lane = t & 31;
    const int g    = lane >> 2;
    const int q    = lane & 3;
    const int b    = blockIdx.z;
    const int sb   = blockIdx.y * SHALF;
    const int xi   = blockIdx.x * 4 + warp;

    // ---- stage this block's yu half ----
    for (int i = t; i < SHALF; i += TPB) {
        const float2* row = (const float2*)(yu + ((size_t)b * SS_DIM + sb + i) * (CC + DD));
        const float2 a0 = row[0], a1 = row[1], a2 = row[2], a3 = row[3], yv = row[4];
        float2* ur = (float2*)&s_u[i][0];
        ur[0] = a0; ur[1] = a1; ur[2] = a2; ur[3] = a3;
        s_y[i] = yv;
    }
    __syncthreads();

    // ---- per-lane loop-invariant constants in registers (broadcast L1 loads) ----
    const int j0 = 2 * q, j2 = 8 + 2 * q;
    const float bout = gbout[0];
    const float2 wiA = make_float2(gWin[j0], gWin[j0 + 1]);
    const float2 wiB = make_float2(gWin[j2], gWin[j2 + 1]);
    const float2 biA = make_float2(gbin[j0], gbin[j0 + 1]);
    const float2 biB = make_float2(gbin[j2], gbin[j2 + 1]);
    const float2 woA = make_float2(gWout[j0], gWout[j0 + 1]);
    const float2 woB = make_float2(gWout[j2], gWout[j2 + 1]);

    float2 bh[DEPTH][2];
#pragma unroll
    for (int l = 0; l < DEPTH; ++l) {
        bh[l][0] = make_float2(gbhid[l * WIDTH + j0], gbhid[l * WIDTH + j0 + 1]);
        bh[l][1] = make_float2(gbhid[l * WIDTH + j2], gbhid[l * WIDTH + j2 + 1]);
    }

    // B fragments, single fp16 (R15 numerics)
    unsigned Bf[DEPTH][2][2];
#pragma unroll
    for (int l = 0; l < DEPTH; ++l) {
        const float* Wl = gWhid + l * WIDTH * WIDTH;
#pragma unroll
        for (int nt = 0; nt < 2; ++nt) {
            const int n = g + 8 * nt;
            Bf[l][nt][0] = pack_f16x2(Wl[(2 * q) * WIDTH + n],
                                      Wl[(2 * q + 1) * WIDTH + n]);
            Bf[l][nt][1] = pack_f16x2(Wl[(2 * q + 8) * WIDTH + n],
                                      Wl[(2 * q + 9) * WIDTH + n]);
        }
    }

    const float2 xv = *(const float2*)(xin + ((size_t)b * XX + xi) * DD);

    float acc0 = 0.0f, acc1 = 0.0f;

#pragma unroll 1
    for (int ch = 0; ch < NPAIR; ++ch) {
        const int sA = ch * 32;
        const int sB = sA + SHALF / 2;   // second stream, +256

        // r for both streams
        float rg[2][4];
        {
            const float2 yvA = s_y[sA + lane];
            const float2 yvB = s_y[sB + lane];
            float dx = xv.x - yvA.x, dy = xv.y - yvA.y;
            const float rA = fmaf(dy, dy, dx * dx);
            dx = xv.x - yvB.x; dy = xv.y - yvB.y;
            const float rB = fmaf(dy, dy, dx * dx);
            rg[0][0] = __shfl_sync(0xffffffffu, rA, g);
            rg[0][1] = __shfl_sync(0xffffffffu, rA, g + 8);
            rg[0][2] = __shfl_sync(0xffffffffu, rA, g + 16);
            rg[0][3] = __shfl_sync(0xffffffffu, rA, g + 24);
            rg[1][0] = __shfl_sync(0xffffffffu, rB, g);
            rg[1][1] = __shfl_sync(0xffffffffu, rB, g + 8);
            rg[1][2] = __shfl_sync(0xffffffffu, rB, g + 16);
            rg[1][3] = __shfl_sync(0xffffffffu, rB, g + 24);
        }

        // h in f32, D-fragment layout, two streams: hD[st][mt][nt][c]
        float hD[2][2][2][4];
#pragma unroll
        for (int st = 0; st < 2; ++st)
#pragma unroll
            for (int nt = 0; nt < 2; ++nt) {
                const float2 wv = nt ? wiB : wiA;
                const float2 bv = nt ? biB : biA;
                hD[st][0][nt][0] = fmaf(rg[st][0], wv.x, bv.x);
                hD[st][0][nt][1] = fmaf(rg[st][0], wv.y, bv.y);
                hD[st][0][nt][2] = fmaf(rg[st][1], wv.x, bv.x);
                hD[st][0][nt][3] = fmaf(rg[st][1], wv.y, bv.y);
                hD[st][1][nt][0] = fmaf(rg[st][2], wv.x, bv.x);
                hD[st][1][nt][1] = fmaf(rg[st][2], wv.y, bv.y);
                hD[st][1][nt][2] = fmaf(rg[st][3], wv.x, bv.x);
                hD[st][1][nt][3] = fmaf(rg[st][3], wv.y, bv.y);
            }

#pragma unroll
        for (int l = 0; l < DEPTH; ++l) {
#pragma unroll
            for (int st = 0; st < 2; ++st) {
#pragma unroll
                for (int mt = 0; mt < 2; ++mt) {
                    unsigned a[4];
                    a[0] = pack_f16x2(hD[st][mt][0][0], hD[st][mt][0][1]);
                    a[1] = pack_f16x2(hD[st][mt][0][2], hD[st][mt][0][3]);
                    a[2] = pack_f16x2(hD[st][mt][1][0], hD[st][mt][1][1]);
                    a[3] = pack_f16x2(hD[st][mt][1][2], hD[st][mt][1][3]);
                    float z0[4], z1[4];
                    mma_f16_init(z0, a, Bf[l][0][0], Bf[l][0][1],
                                 bh[l][0].x, bh[l][0].y);
                    mma_f16_init(z1, a, Bf[l][1][0], Bf[l][1][1],
                                 bh[l][1].x, bh[l][1].y);
#pragma unroll
                    for (int c = 0; c < 4; ++c) {
                        hD[st][mt][0][c] += fast_tanh(z0[c]);
                        hD[st][mt][1][c] += fast_tanh(z1[c]);
                    }
                }
            }
        }

        // epilogue: k per stream, quad-reduce, accumulate u
#pragma unroll
        for (int st = 0; st < 2; ++st) {
            const int s0 = st ? sB : sA;
            float k[4];
#pragma unroll
            for (int mt = 0; mt < 2; ++mt) {
                float pg  = fmaf(hD[st][mt][0][0], woA.x,
                            fmaf(hD[st][mt][0][1], woA.y,
                            fmaf(hD[st][mt][1][0], woB.x, hD[st][mt][1][1] * woB.y)));
                float pg8 = fmaf(hD[st][mt][0][2], woA.x,
                            fmaf(hD[st][mt][0][3], woA.y,
                            fmaf(hD[st][mt][1][2], woB.x, hD[st][mt][1][3] * woB.y)));
                pg  += __shfl_xor_sync(0xffffffffu, pg, 1);
                pg  += __shfl_xor_sync(0xffffffffu, pg, 2);
                pg8 += __shfl_xor_sync(0xffffffffu, pg8, 1);
                pg8 += __shfl_xor_sync(0xffffffffu, pg8, 2);
                k[2 * mt]     = pg + bout;
                k[2 * mt + 1] = pg8 + bout;
            }
            const int srow[4] = {s0 + g, s0 + g + 8, s0 + 16 + g, s0 + 24 + g};
#pragma unroll
            for (int i = 0; i < 4; ++i) {
                const float2 uv = *(const float2*)&s_u[srow[i]][2 * q];
                acc0 = fmaf(k[i], uv.x, acc0);
                acc1 = fmaf(k[i], uv.y, acc1);
            }
        }
    }

#pragma unroll
    for (int off = 4; off < 32; off <<= 1) {
        acc0 += __shfl_xor_sync(0xffffffffu, acc0, off);
        acc1 += __shfl_xor_sync(0xffffffffu, acc1, off);
    }
    if (lane < 4) {
        const float invS = 1.0f / (float)SS_DIM;
        float* op = out + ((size_t)b * XX + xi) * CC + 2 * lane;
        atomicAdd(op,     acc0 * invS);
        atomicAdd(op + 1, acc1 * invS);
    }
}

extern "C" void kernel_launch(void* const* d_in, const int* in_sizes, int n_in,
                              void* d_out, int out_size) {
    const float* yu    = (const float*)d_in[0]; // (4,1024,10)
    const float* x     = (const float*)d_in[1]; // (4,1024,2)
    const float* W_in  = (const float*)d_in[2]; // (1,16)
    const float* b_in  = (const float*)d_in[3]; // (16,)
    const float* W_hid = (const float*)d_in[4]; // (4,16,16)
    const float* b_hid = (const float*)d_in[5]; // (4,16)
    const float* W_out = (const float*)d_in[6]; // (16,1)
    const float* b_out = (const float*)d_in[7]; // (1,)

    (void)in_sizes; (void)n_in;

    cudaMemsetAsync(d_out, 0, (size_t)out_size * sizeof(float), 0);

    dim3 grid(XX / 4, SS_DIM / SHALF, BB);   // 2048 blocks
    ccl_kernel<<<grid, TPB, 0, 0>>>(yu, x, W_in, b_in, W_hid, b_hid, W_out, b_out,
                                    (float*)d_out);
}